// round 15
// baseline (speedup 1.0000x reference)
#include <cuda_runtime.h>
#include <math.h>
#include <cstdint>

#define NB   8192
#define HD   1024
#define OUTW 2050   // h_new(1024) | c_new(1024) | alpha | beta

// ---------------- scratch (__device__ globals; no allocation allowed) ------
__device__ float g_i[(size_t)NB * HD];
__device__ float g_f[(size_t)NB * HD];
__device__ float g_cp[(size_t)NB * HD];     // tanh(cand)
__device__ float g_cnew[(size_t)NB * HD];   // exact c_new
__device__ float g_cnr[(size_t)NB * HD];    // tf32-rounded c_new (MMA operand)
__device__ float g_hnew[(size_t)NB * HD];
__device__ float g_micro[(size_t)NB * 64];
// tf32-rounded activation copies (MMA A operands)
__device__ float g_xr[(size_t)NB * HD];
__device__ float g_hr[(size_t)NB * HD];
__device__ float g_cr[(size_t)NB * HD];
// transposed + tf32-rounded weights: Wt[n][k]
__device__ float g_Wt_i[(size_t)3072 * 1024];
__device__ float g_Wt_f[(size_t)3072 * 1024];
__device__ float g_Wt_o[(size_t)3072 * 1024];
__device__ float g_Wt_c[(size_t)2048 * 1024];

__device__ __forceinline__ float sigm(float v) { return 1.0f / (1.0f + expf(-v)); }

__device__ __forceinline__ float tf32_round(float x) {
    uint32_t u;
    asm("cvt.rna.tf32.f32 %0, %1;" : "=r"(u) : "f"(x));
    return __uint_as_float(u);
}
__device__ __forceinline__ float4 tf32_round4(float4 v) {
    float4 r;
    r.x = tf32_round(v.x); r.y = tf32_round(v.y);
    r.z = tf32_round(v.z); r.w = tf32_round(v.w);
    return r;
}

__device__ __forceinline__ uint32_t smem_u32(const void* p) {
    uint32_t a;
    asm("{ .reg .u64 t; cvta.to.shared.u64 t, %1; cvt.u32.u64 %0, t; }" : "=r"(a) : "l"(p));
    return a;
}
__device__ __forceinline__ void cp16(uint32_t dst, const float* src) {
    asm volatile("cp.async.cg.shared.global [%0], [%1], 16;" :: "r"(dst), "l"(src));
}
#define CP_COMMIT() asm volatile("cp.async.commit_group;" ::: "memory")

// m16n8k8 tf32 MMA (sm_80 baseline PTX -> legal on plain sm_103 target)
__device__ __forceinline__ void mma8(float& d0, float& d1, float& d2, float& d3,
                                     uint32_t a0, uint32_t a1, uint32_t a2, uint32_t a3,
                                     uint32_t b0, uint32_t b1) {
    asm volatile(
        "mma.sync.aligned.m16n8k8.row.col.f32.tf32.tf32.f32 "
        "{%0,%1,%2,%3}, {%4,%5,%6,%7}, {%8,%9}, {%0,%1,%2,%3};"
        : "+f"(d0), "+f"(d1), "+f"(d2), "+f"(d3)
        : "r"(a0), "r"(a1), "r"(a2), "r"(a3), "r"(b0), "r"(b1));
}

// ---------------------------------------------------------------------------
// Pre-round x,h,c to tf32 copies (float4 streaming pass)
// ---------------------------------------------------------------------------
__global__ __launch_bounds__(256) void round_xhc(const float* __restrict__ x,
                                                 const float* __restrict__ h,
                                                 const float* __restrict__ c)
{
    const size_t i = ((size_t)blockIdx.x * 256 + threadIdx.x) * 4;
    *reinterpret_cast<float4*>(g_xr + i) =
        tf32_round4(*reinterpret_cast<const float4*>(x + i));
    *reinterpret_cast<float4*>(g_hr + i) =
        tf32_round4(*reinterpret_cast<const float4*>(h + i));
    *reinterpret_cast<float4*>(g_cr + i) =
        tf32_round4(*reinterpret_cast<const float4*>(c + i));
}

// ---------------------------------------------------------------------------
// Merged W transpose + tf32 round: z selects which weight matrix.
// W[K][1024] -> Wt[1024][K];  z=0:Wi  z=1:Wf  z=2:Wo (K=3072)  z=3:Wcand (K=2048)
// ---------------------------------------------------------------------------
__global__ __launch_bounds__(256) void transW_all(
    const float* __restrict__ W0, const float* __restrict__ W1,
    const float* __restrict__ W2, const float* __restrict__ W3,
    float* __restrict__ T0, float* __restrict__ T1,
    float* __restrict__ T2, float* __restrict__ T3)
{
    const int z = blockIdx.z;
    const int K = (z == 3) ? 2048 : 3072;
    const int k0 = blockIdx.y * 32;
    if (k0 >= K) return;
    const float* W = (z == 0) ? W0 : (z == 1) ? W1 : (z == 2) ? W2 : W3;
    float* Wt      = (z == 0) ? T0 : (z == 1) ? T1 : (z == 2) ? T2 : T3;

    __shared__ float tile[32][33];
    const int n0 = blockIdx.x * 32;
    const int tx = threadIdx.x, ty = threadIdx.y;
    #pragma unroll
    for (int i = ty; i < 32; i += 8)
        tile[i][tx] = W[(size_t)(k0 + i) * 1024 + n0 + tx];
    __syncthreads();
    #pragma unroll
    for (int i = ty; i < 32; i += 8)
        Wt[(size_t)(n0 + i) * K + k0 + tx] = tf32_round(tile[tx][i]);
}

// ---------------------------------------------------------------------------
// Merged gates GEMM (i / f / cand selected by blockIdx.z; cand last in
// dispatch order). C = act(concat @ W + b); block 128x128, BK=16, 8 warps,
// warp tile 64x32, 2 CTAs/SM, 3-stage cp.async ring, ONE sync per chunk.
//   z=0: [x,h,c]@Wi  -> g_i  = sigmoid   (K=3072)
//   z=1: [x,h,c]@Wf  -> g_f  = sigmoid   (K=3072)
//   z=2: [x,h]@Wcand -> g_cp = tanh      (K=2048)
// ---------------------------------------------------------------------------
__global__ __launch_bounds__(256, 2) void gemm_gates(
    const float* __restrict__ A0, const float* __restrict__ A1,
    const float* __restrict__ A2,
    const float* __restrict__ Wt0, const float* __restrict__ Wt1,
    const float* __restrict__ Wt2,
    const float* __restrict__ b0, const float* __restrict__ b1,
    const float* __restrict__ b2)
{
    constexpr int LDS = 20;                  // padded stride (words)
    constexpr int STG_WORDS = 256 * LDS;     // one stage: A(128) + B(128) rows

    extern __shared__ __align__(16) float sm[];   // [3][256][LDS]

    const int z   = blockIdx.z;
    const int K   = (z == 2) ? 2048 : 3072;
    const int NCH = K / 16;
    const float* Wt   = (z == 0) ? Wt0 : (z == 1) ? Wt1 : Wt2;
    const float* bias = (z == 0) ? b0  : (z == 1) ? b1  : b2;
    float* dst        = (z == 0) ? g_i : (z == 1) ? g_f : g_cp;

    const int tid  = threadIdx.x;
    const int lane = tid & 31;
    const int wid  = tid >> 5;
    const int warp_m = wid & 1;    // 0..1 -> row offset *64
    const int warp_n = wid >> 1;   // 0..3 -> col offset *32
    const int grp = lane >> 2;     // 0..7
    const int qid = lane & 3;      // 0..3
    const int row0 = blockIdx.y * 128;
    const int n0   = blockIdx.x * 128;

    // staging mapping: thread covers rows r_s and r_s+64, 4 floats at kq4
    const int r_s = tid >> 2;          // 0..63
    const int kq4 = (tid & 3) * 4;     // 0,4,8,12

    const uint32_t smb = smem_u32(sm);
    const uint32_t sA0 = smb + ((uint32_t)r_s * LDS + kq4) * 4u;
    const uint32_t sB0 = smb + ((uint32_t)(128 + r_s) * LDS + kq4) * 4u;
    constexpr uint32_t ROW64 = 64u * LDS * 4u;
    constexpr uint32_t STG   = (uint32_t)STG_WORDS * 4u;

    float acc[4][4][4];
    #pragma unroll
    for (int i = 0; i < 4; i++)
        #pragma unroll
        for (int j = 0; j < 4; j++)
            #pragma unroll
            for (int v = 0; v < 4; v++) acc[i][j][v] = 0.0f;

    auto issue = [&](int cc) {
        const int kt = cc * 16;
        const float* seg = (kt < 1024) ? A0 : ((kt < 2048) ? A1 : A2);
        const int kin = (kt & 1023) + kq4;
        const uint32_t bo = (uint32_t)(cc % 3) * STG;
        cp16(sA0 + bo,         seg + (size_t)(row0 + r_s) * HD + kin);
        cp16(sA0 + bo + ROW64, seg + (size_t)(row0 + r_s + 64) * HD + kin);
        cp16(sB0 + bo,         Wt + (size_t)(n0 + r_s) * K + kt + kq4);
        cp16(sB0 + bo + ROW64, Wt + (size_t)(n0 + r_s + 64) * K + kt + kq4);
    };

    issue(0); CP_COMMIT();
    issue(1); CP_COMMIT();

    for (int c = 0; c < NCH; c++) {
        if (c + 1 < NCH)
            asm volatile("cp.async.wait_group 1;" ::: "memory");  // chunk c landed
        else
            asm volatile("cp.async.wait_group 0;" ::: "memory");
        __syncthreads();   // chunk c visible; buf[(c+2)%3] reads (chunk c-1) done

        if (c + 2 < NCH) { issue(c + 2); CP_COMMIT(); }

        const float* Ab = sm + (c % 3) * STG_WORDS;
        const float* Bb = Ab + 128 * LDS;

        #pragma unroll
        for (int kk = 0; kk < 16; kk += 8) {
            uint32_t af[4][4], bf[4][2];
            #pragma unroll
            for (int i = 0; i < 4; i++) {
                const int r = warp_m * 64 + i * 16 + grp;
                af[i][0] = __float_as_uint(Ab[(r)     * LDS + kk + qid]);
                af[i][1] = __float_as_uint(Ab[(r + 8) * LDS + kk + qid]);
                af[i][2] = __float_as_uint(Ab[(r)     * LDS + kk + qid + 4]);
                af[i][3] = __float_as_uint(Ab[(r + 8) * LDS + kk + qid + 4]);
            }
            #pragma unroll
            for (int j = 0; j < 4; j++) {
                const int n = warp_n * 32 + j * 8 + grp;
                bf[j][0] = __float_as_uint(Bb[n * LDS + kk + qid]);
                bf[j][1] = __float_as_uint(Bb[n * LDS + kk + qid + 4]);
            }
            #pragma unroll
            for (int i = 0; i < 4; i++)
                #pragma unroll
                for (int j = 0; j < 4; j++)
                    mma8(acc[i][j][0], acc[i][j][1], acc[i][j][2], acc[i][j][3],
                         af[i][0], af[i][1], af[i][2], af[i][3],
                         bf[j][0], bf[j][1]);
        }
    }

    // epilogue
    const bool is_sig = (z < 2);
    #pragma unroll
    for (int i = 0; i < 4; i++) {
        const size_t r = (size_t)(row0 + warp_m * 64 + i * 16 + grp);
        #pragma unroll
        for (int j = 0; j < 4; j++) {
            const int n = n0 + warp_n * 32 + j * 8 + qid * 2;
            #pragma unroll
            for (int v = 0; v < 4; v++) {
                const size_t rr = r + (v >= 2 ? 8 : 0);
                const int nn = n + (v & 1);
                float val = acc[i][j][v] + __ldg(bias + nn);
                dst[rr * HD + nn] = is_sig ? sigm(val) : tanhf(val);
            }
        }
    }
}

// ---------------------------------------------------------------------------
// c_new = f*c + i*cp  -> g_cnew (exact), g_cnr (tf32), dout[:,1024:2048]
// ---------------------------------------------------------------------------
__global__ __launch_bounds__(256) void cnew_kernel(const float* __restrict__ c,
                                                   float* __restrict__ dout)
{
    const size_t i = ((size_t)blockIdx.x * 256 + threadIdx.x) * 4;
    float4 f4 = *reinterpret_cast<const float4*>(g_f + i);
    float4 i4 = *reinterpret_cast<const float4*>(g_i + i);
    float4 p4 = *reinterpret_cast<const float4*>(g_cp + i);
    float4 c4 = *reinterpret_cast<const float4*>(c + i);
    float4 cn;
    cn.x = fmaf(f4.x, c4.x, i4.x * p4.x);
    cn.y = fmaf(f4.y, c4.y, i4.y * p4.y);
    cn.z = fmaf(f4.z, c4.z, i4.z * p4.z);
    cn.w = fmaf(f4.w, c4.w, i4.w * p4.w);
    *reinterpret_cast<float4*>(g_cnew + i) = cn;
    *reinterpret_cast<float4*>(g_cnr + i) = tf32_round4(cn);
    const size_t b = i >> 10;
    const int j = (int)(i & 1023);
    float* drow = dout + b * OUTW + HD + j;
    drow[0] = cn.x; drow[1] = cn.y; drow[2] = cn.z; drow[3] = cn.w;
}

// ---------------------------------------------------------------------------
// o-gate GEMM: [x,h,cnew_r]@Wo -> h_new = sig(o)*tanh(cnew) -> g_hnew + dout
// Same tiling; 3-stage ring, one sync per chunk. K=3072.
// ---------------------------------------------------------------------------
__global__ __launch_bounds__(256, 2) void gemm_o(
    const float* __restrict__ A0, const float* __restrict__ A1,
    const float* __restrict__ A2, const float* __restrict__ Wt,
    const float* __restrict__ bias, float* __restrict__ dout)
{
    constexpr int K   = 3072;
    constexpr int NCH = K / 16;
    constexpr int LDS = 20;
    constexpr int STG_WORDS = 256 * LDS;

    extern __shared__ __align__(16) float sm[];

    const int tid  = threadIdx.x;
    const int lane = tid & 31;
    const int wid  = tid >> 5;
    const int warp_m = wid & 1;
    const int warp_n = wid >> 1;
    const int grp = lane >> 2;
    const int qid = lane & 3;
    const int row0 = blockIdx.y * 128;
    const int n0   = blockIdx.x * 128;

    const int r_s = tid >> 2;
    const int kq4 = (tid & 3) * 4;

    const uint32_t smb = smem_u32(sm);
    const uint32_t sA0 = smb + ((uint32_t)r_s * LDS + kq4) * 4u;
    const uint32_t sB0 = smb + ((uint32_t)(128 + r_s) * LDS + kq4) * 4u;
    constexpr uint32_t ROW64 = 64u * LDS * 4u;
    constexpr uint32_t STG   = (uint32_t)STG_WORDS * 4u;

    float acc[4][4][4];
    #pragma unroll
    for (int i = 0; i < 4; i++)
        #pragma unroll
        for (int j = 0; j < 4; j++)
            #pragma unroll
            for (int v = 0; v < 4; v++) acc[i][j][v] = 0.0f;

    auto issue = [&](int cc) {
        const int kt = cc * 16;
        const float* seg = (kt < 1024) ? A0 : ((kt < 2048) ? A1 : A2);
        const int kin = (kt & 1023) + kq4;
        const uint32_t bo = (uint32_t)(cc % 3) * STG;
        cp16(sA0 + bo,         seg + (size_t)(row0 + r_s) * HD + kin);
        cp16(sA0 + bo + ROW64, seg + (size_t)(row0 + r_s + 64) * HD + kin);
        cp16(sB0 + bo,         Wt + (size_t)(n0 + r_s) * K + kt + kq4);
        cp16(sB0 + bo + ROW64, Wt + (size_t)(n0 + r_s + 64) * K + kt + kq4);
    };

    issue(0); CP_COMMIT();
    issue(1); CP_COMMIT();

    for (int c = 0; c < NCH; c++) {
        if (c + 1 < NCH)
            asm volatile("cp.async.wait_group 1;" ::: "memory");
        else
            asm volatile("cp.async.wait_group 0;" ::: "memory");
        __syncthreads();

        if (c + 2 < NCH) { issue(c + 2); CP_COMMIT(); }

        const float* Ab = sm + (c % 3) * STG_WORDS;
        const float* Bb = Ab + 128 * LDS;

        #pragma unroll
        for (int kk = 0; kk < 16; kk += 8) {
            uint32_t af[4][4], bf[4][2];
            #pragma unroll
            for (int i = 0; i < 4; i++) {
                const int r = warp_m * 64 + i * 16 + grp;
                af[i][0] = __float_as_uint(Ab[(r)     * LDS + kk + qid]);
                af[i][1] = __float_as_uint(Ab[(r + 8) * LDS + kk + qid]);
                af[i][2] = __float_as_uint(Ab[(r)     * LDS + kk + qid + 4]);
                af[i][3] = __float_as_uint(Ab[(r + 8) * LDS + kk + qid + 4]);
            }
            #pragma unroll
            for (int j = 0; j < 4; j++) {
                const int n = warp_n * 32 + j * 8 + grp;
                bf[j][0] = __float_as_uint(Bb[n * LDS + kk + qid]);
                bf[j][1] = __float_as_uint(Bb[n * LDS + kk + qid + 4]);
            }
            #pragma unroll
            for (int i = 0; i < 4; i++)
                #pragma unroll
                for (int j = 0; j < 4; j++)
                    mma8(acc[i][j][0], acc[i][j][1], acc[i][j][2], acc[i][j][3],
                         af[i][0], af[i][1], af[i][2], af[i][3],
                         bf[j][0], bf[j][1]);
        }
    }

    #pragma unroll
    for (int i = 0; i < 4; i++) {
        const size_t r = (size_t)(row0 + warp_m * 64 + i * 16 + grp);
        #pragma unroll
        for (int j = 0; j < 4; j++) {
            const int n = n0 + warp_n * 32 + j * 8 + qid * 2;
            #pragma unroll
            for (int v = 0; v < 4; v++) {
                const size_t rr = r + (v >= 2 ? 8 : 0);
                const int nn = n + (v & 1);
                float val = acc[i][j][v] + __ldg(bias + nn);
                float hn = sigm(val) * tanhf(g_cnew[rr * HD + nn]);
                g_hnew[rr * HD + nn] = hn;
                dout[rr * OUTW + nn] = hn;
            }
        }
    }
}

// ---------------------------------------------------------------------------
// micro = h_new @ W_m + b_m : [8192,1024] @ [1024,64]  (FFMA, small)
// ---------------------------------------------------------------------------
__global__ __launch_bounds__(256) void micro_gemm(const float* __restrict__ Wm,
                                                  const float* __restrict__ bm)
{
    __shared__ __align__(16) float As2[16][68];
    __shared__ __align__(16) float Bs2[16][64];

    const int tid  = threadIdx.x;
    const int row0 = blockIdx.x * 64;
    const int arow = tid >> 2;
    const int acol = (tid & 3) * 4;
    const int brow = tid >> 4;
    const int bcol = (tid & 15) * 4;
    const int ty   = tid >> 4;
    const int tx   = tid & 15;

    float acc[4][4];
    #pragma unroll
    for (int i = 0; i < 4; i++)
        #pragma unroll
        for (int j = 0; j < 4; j++) acc[i][j] = 0.0f;

    for (int kt = 0; kt < 1024; kt += 16) {
        float4 av = *reinterpret_cast<const float4*>(
            g_hnew + (size_t)(row0 + arow) * HD + kt + acol);
        As2[acol + 0][arow] = av.x;
        As2[acol + 1][arow] = av.y;
        As2[acol + 2][arow] = av.z;
        As2[acol + 3][arow] = av.w;
        *reinterpret_cast<float4*>(&Bs2[brow][bcol]) =
            *reinterpret_cast<const float4*>(Wm + (size_t)(kt + brow) * 64 + bcol);
        __syncthreads();

        #pragma unroll
        for (int k = 0; k < 16; k++) {
            float4 a = *reinterpret_cast<const float4*>(&As2[k][ty * 4]);
            float4 b = *reinterpret_cast<const float4*>(&Bs2[k][tx * 4]);
            float ar[4] = {a.x, a.y, a.z, a.w};
            float br[4] = {b.x, b.y, b.z, b.w};
            #pragma unroll
            for (int i = 0; i < 4; i++)
                #pragma unroll
                for (int j = 0; j < 4; j++)
                    acc[i][j] = fmaf(ar[i], br[j], acc[i][j]);
        }
        __syncthreads();
    }

    #pragma unroll
    for (int i = 0; i < 4; i++) {
        const int r = row0 + ty * 4 + i;
        #pragma unroll
        for (int j = 0; j < 4; j++) {
            const int n = tx * 4 + j;
            g_micro[(size_t)r * 64 + n] = acc[i][j] + bm[n];
        }
    }
}

// ---------------------------------------------------------------------------
// Tail: gumbel-softmax attention + alpha/beta (one block per batch row)
// ---------------------------------------------------------------------------
__global__ __launch_bounds__(128) void tail_kernel(
    const float* __restrict__ x, const float* __restrict__ memory,
    const float* __restrict__ u_gs, const float* __restrict__ u_a,
    const float* __restrict__ u_b,
    const float* __restrict__ w_a_h, const float* __restrict__ w_a_x,
    const float* __restrict__ w_a_r,
    const float* __restrict__ w_b_h, const float* __restrict__ w_b_x,
    const float* __restrict__ w_b_r,
    float* __restrict__ dout)
{
    const int b = blockIdx.x;
    const int t = threadIdx.x;

    __shared__ float smicro[64];
    __shared__ float slog[16];
    __shared__ float sattn[16];
    __shared__ float ssamp[64];
    __shared__ float red[6 * 128];

    const float* mem = memory + (size_t)b * 16 * 64;

    if (t < 64) smicro[t] = g_micro[(size_t)b * 64 + t];
    __syncthreads();

    if (t < 16) {
        float a = 0.0f;
        #pragma unroll 8
        for (int k = 0; k < 64; k++) a = fmaf(mem[t * 64 + k], smicro[k], a);
        float u = u_gs[b * 16 + t];
        slog[t] = a + (-logf(-logf(u)));
    }
    __syncthreads();

    if (t == 0) {
        float mx = -1e30f;
        for (int m = 0; m < 16; m++) mx = fmaxf(mx, slog[m]);
        float e[16], s = 0.0f;
        for (int m = 0; m < 16; m++) { e[m] = expf(slog[m] - mx); s += e[m]; }
        float inv = 1.0f / s;
        for (int m = 0; m < 16; m++) sattn[m] = e[m] * inv;
    }
    __syncthreads();

    if (t < 64) {
        float s = 0.0f;
        #pragma unroll
        for (int m = 0; m < 16; m++) s = fmaf(mem[m * 64 + t], sattn[m], s);
        ssamp[t] = s + 1.0f;
    }
    __syncthreads();

    const float* hrow = g_hnew + (size_t)b * HD;
    const float* xrow = x + (size_t)b * HD;
    float pah = 0.f, pax = 0.f, pbh = 0.f, pbx = 0.f, par = 0.f, pbr = 0.f;
    for (int k = t; k < HD; k += 128) {
        float hv = hrow[k], xv = xrow[k];
        pah = fmaf(hv, w_a_h[k], pah);
        pbh = fmaf(hv, w_b_h[k], pbh);
        pax = fmaf(xv, w_a_x[k], pax);
        pbx = fmaf(xv, w_b_x[k], pbx);
    }
    if (t < 64) {
        float sv = ssamp[t];
        par = sv * w_a_r[t];
        pbr = sv * w_b_r[t];
    }
    red[0 * 128 + t] = pah;
    red[1 * 128 + t] = pax;
    red[2 * 128 + t] = par;
    red[3 * 128 + t] = pbh;
    red[4 * 128 + t] = pbx;
    red[5 * 128 + t] = pbr;
    __syncthreads();

    for (int s = 64; s > 0; s >>= 1) {
        if (t < s) {
            #pragma unroll
            for (int v = 0; v < 6; v++) red[v * 128 + t] += red[v * 128 + t + s];
        }
        __syncthreads();
    }

    if (t == 0) {
        float ua = u_a[b], ub = u_b[b];
        float la = logf(ua) - log1pf(-ua);
        float lb = logf(ub) - log1pf(-ub);
        float alpha = sigm(red[0] + red[128] + red[256] + la);
        float beta  = sigm(red[384] + red[512] + red[640] + lb);
        dout[(size_t)b * OUTW + 2048] = alpha;
        dout[(size_t)b * OUTW + 2049] = beta;
    }
}

// ---------------------------------------------------------------------------
extern "C" void kernel_launch(void* const* d_in, const int* in_sizes, int n_in,
                              void* d_out, int out_size)
{
    const float* x      = (const float*)d_in[0];
    const float* h      = (const float*)d_in[1];
    const float* c      = (const float*)d_in[2];
    const float* memory = (const float*)d_in[3];
    const float* u_gs   = (const float*)d_in[4];
    const float* u_a    = (const float*)d_in[5];
    const float* u_b    = (const float*)d_in[6];
    const float* W_i    = (const float*)d_in[7];
    const float* b_i    = (const float*)d_in[8];
    const float* W_f    = (const float*)d_in[9];
    const float* b_f    = (const float*)d_in[10];
    const float* W_o    = (const float*)d_in[11];
    const float* b_o    = (const float*)d_in[12];
    const float* W_cand = (const float*)d_in[13];
    const float* b_cand = (const float*)d_in[14];
    const float* W_m    = (const float*)d_in[15];
    const float* b_m    = (const float*)d_in[16];
    const float* w_a_h  = (const float*)d_in[17];
    const float* w_a_x  = (const float*)d_in[18];
    const float* w_a_r  = (const float*)d_in[19];
    const float* w_b_h  = (const float*)d_in[20];
    const float* w_b_x  = (const float*)d_in[21];
    const float* w_b_r  = (const float*)d_in[22];
    float* out = (float*)d_out;

    float* wt_i; cudaGetSymbolAddress((void**)&wt_i, g_Wt_i);
    float* wt_f; cudaGetSymbolAddress((void**)&wt_f, g_Wt_f);
    float* wt_o; cudaGetSymbolAddress((void**)&wt_o, g_Wt_o);
    float* wt_c; cudaGetSymbolAddress((void**)&wt_c, g_Wt_c);
    float* xr;   cudaGetSymbolAddress((void**)&xr,   g_xr);
    float* hr;   cudaGetSymbolAddress((void**)&hr,   g_hr);
    float* cr;   cudaGetSymbolAddress((void**)&cr,   g_cr);
    float* cnr;  cudaGetSymbolAddress((void**)&cnr,  g_cnr);

    const int SMEM_DYN = 3 * 256 * 20 * 4;  // 61440 bytes (3-stage ring)
    static bool attr_set = false;
    if (!attr_set) {
        cudaFuncSetAttribute(gemm_gates, cudaFuncAttributeMaxDynamicSharedMemorySize, SMEM_DYN);
        cudaFuncSetAttribute(gemm_o,     cudaFuncAttributeMaxDynamicSharedMemorySize, SMEM_DYN);
        attr_set = true;
    }

    round_xhc<<<(NB * HD) / (256 * 4), 256>>>(x, h, c);
    transW_all<<<dim3(32, 96, 4), dim3(32, 8)>>>(W_i, W_f, W_o, W_cand,
                                                 wt_i, wt_f, wt_o, wt_c);

    // merged i/f/cand gates (cand last in dispatch order)
    gemm_gates<<<dim3(8, 64, 3), 256, SMEM_DYN>>>(xr, hr, cr, wt_i, wt_f, wt_c,
                                                  b_i, b_f, b_cand);
    cnew_kernel<<<(NB * HD) / (256 * 4), 256>>>(c, out);
    gemm_o<<<dim3(8, 64), 256, SMEM_DYN>>>(xr, hr, cnr, wt_o, b_o, out);
    micro_gemm<<<NB / 64, 256>>>(W_m, b_m);
    tail_kernel<<<NB, 128>>>(x, memory, u_gs, u_a, u_b,
                             w_a_h, w_a_x, w_a_r, w_b_h, w_b_x, w_b_r, out);
}

// round 16
// speedup vs baseline: 1.0441x; 1.0441x over previous
#include <cuda_runtime.h>
#include <math.h>
#include <cstdint>

#define NB   8192
#define HD   1024
#define OUTW 2050   // h_new(1024) | c_new(1024) | alpha | beta

// ---------------- scratch (__device__ globals; no allocation allowed) ------
__device__ float g_i[(size_t)NB * HD];
__device__ float g_f[(size_t)NB * HD];
__device__ float g_cp[(size_t)NB * HD];     // tanh(cand)
__device__ float g_cnew[(size_t)NB * HD];   // exact c_new
__device__ float g_cnr[(size_t)NB * HD];    // tf32-rounded c_new (MMA operand)
__device__ float g_hnew[(size_t)NB * HD];
__device__ float g_micro[(size_t)NB * 64];
// tf32-rounded activation copies (MMA A operands)
__device__ float g_xr[(size_t)NB * HD];
__device__ float g_hr[(size_t)NB * HD];
__device__ float g_cr[(size_t)NB * HD];
// transposed + tf32-rounded weights: Wt[n][k]
__device__ float g_Wt_i[(size_t)3072 * 1024];
__device__ float g_Wt_f[(size_t)3072 * 1024];
__device__ float g_Wt_o[(size_t)3072 * 1024];
__device__ float g_Wt_c[(size_t)2048 * 1024];

__device__ __forceinline__ float sigm(float v) { return 1.0f / (1.0f + expf(-v)); }

__device__ __forceinline__ float tf32_round(float x) {
    uint32_t u;
    asm("cvt.rna.tf32.f32 %0, %1;" : "=r"(u) : "f"(x));
    return __uint_as_float(u);
}
__device__ __forceinline__ float4 tf32_round4(float4 v) {
    float4 r;
    r.x = tf32_round(v.x); r.y = tf32_round(v.y);
    r.z = tf32_round(v.z); r.w = tf32_round(v.w);
    return r;
}

__device__ __forceinline__ uint32_t smem_u32(const void* p) {
    uint32_t a;
    asm("{ .reg .u64 t; cvta.to.shared.u64 t, %1; cvt.u32.u64 %0, t; }" : "=r"(a) : "l"(p));
    return a;
}
__device__ __forceinline__ void cp16(uint32_t dst, const float* src) {
    asm volatile("cp.async.cg.shared.global [%0], [%1], 16;" :: "r"(dst), "l"(src));
}
#define CP_COMMIT() asm volatile("cp.async.commit_group;" ::: "memory")

// m16n8k8 tf32 MMA (sm_80 baseline PTX -> legal on plain sm_103 target)
__device__ __forceinline__ void mma8(float& d0, float& d1, float& d2, float& d3,
                                     uint32_t a0, uint32_t a1, uint32_t a2, uint32_t a3,
                                     uint32_t b0, uint32_t b1) {
    asm volatile(
        "mma.sync.aligned.m16n8k8.row.col.f32.tf32.tf32.f32 "
        "{%0,%1,%2,%3}, {%4,%5,%6,%7}, {%8,%9}, {%0,%1,%2,%3};"
        : "+f"(d0), "+f"(d1), "+f"(d2), "+f"(d3)
        : "r"(a0), "r"(a1), "r"(a2), "r"(a3), "r"(b0), "r"(b1));
}

// ---------------------------------------------------------------------------
// Pre-round x,h,c to tf32 copies (float4 streaming pass)
// ---------------------------------------------------------------------------
__global__ __launch_bounds__(256) void round_xhc(const float* __restrict__ x,
                                                 const float* __restrict__ h,
                                                 const float* __restrict__ c)
{
    const size_t i = ((size_t)blockIdx.x * 256 + threadIdx.x) * 4;
    *reinterpret_cast<float4*>(g_xr + i) =
        tf32_round4(*reinterpret_cast<const float4*>(x + i));
    *reinterpret_cast<float4*>(g_hr + i) =
        tf32_round4(*reinterpret_cast<const float4*>(h + i));
    *reinterpret_cast<float4*>(g_cr + i) =
        tf32_round4(*reinterpret_cast<const float4*>(c + i));
}

// ---------------------------------------------------------------------------
// Merged W transpose + tf32 round: z selects which weight matrix.
// W[K][1024] -> Wt[1024][K];  z=0:Wi  z=1:Wf  z=2:Wo (K=3072)  z=3:Wcand (K=2048)
// ---------------------------------------------------------------------------
__global__ __launch_bounds__(256) void transW_all(
    const float* __restrict__ W0, const float* __restrict__ W1,
    const float* __restrict__ W2, const float* __restrict__ W3,
    float* __restrict__ T0, float* __restrict__ T1,
    float* __restrict__ T2, float* __restrict__ T3)
{
    const int z = blockIdx.z;
    const int K = (z == 3) ? 2048 : 3072;
    const int k0 = blockIdx.y * 32;
    if (k0 >= K) return;
    const float* W = (z == 0) ? W0 : (z == 1) ? W1 : (z == 2) ? W2 : W3;
    float* Wt      = (z == 0) ? T0 : (z == 1) ? T1 : (z == 2) ? T2 : T3;

    __shared__ float tile[32][33];
    const int n0 = blockIdx.x * 32;
    const int tx = threadIdx.x, ty = threadIdx.y;
    #pragma unroll
    for (int i = ty; i < 32; i += 8)
        tile[i][tx] = W[(size_t)(k0 + i) * 1024 + n0 + tx];
    __syncthreads();
    #pragma unroll
    for (int i = ty; i < 32; i += 8)
        Wt[(size_t)(n0 + i) * K + k0 + tx] = tf32_round(tile[tx][i]);
}

// ---------------------------------------------------------------------------
// Merged gates GEMM (i / f / cand selected by blockIdx.z; cand last in
// dispatch order). C = act(concat @ W + b); block 128x128, BK=32, 8 warps,
// warp tile 64x32, 2 CTAs/SM, double-buffered cp.async (R13 pattern).
//   z=0: [x,h,c]@Wi  -> g_i  = sigmoid   (K=3072)
//   z=1: [x,h,c]@Wf  -> g_f  = sigmoid   (K=3072)
//   z=2: [x,h]@Wcand -> g_cp = tanh      (K=2048)
// ---------------------------------------------------------------------------
__global__ __launch_bounds__(256, 2) void gemm_gates(
    const float* __restrict__ A0, const float* __restrict__ A1,
    const float* __restrict__ A2,
    const float* __restrict__ Wt0, const float* __restrict__ Wt1,
    const float* __restrict__ Wt2,
    const float* __restrict__ b0, const float* __restrict__ b1,
    const float* __restrict__ b2)
{
    constexpr int LDS = 36;                  // 32 data + 4 pad words per row
    constexpr int STG_WORDS = 256 * LDS;     // one stage: A(128) + B(128) rows

    extern __shared__ __align__(16) float sm[];   // [2][256][LDS]

    const int z   = blockIdx.z;
    const int K   = (z == 2) ? 2048 : 3072;
    const int NCH = K / 32;
    const float* Wt   = (z == 0) ? Wt0 : (z == 1) ? Wt1 : Wt2;
    const float* bias = (z == 0) ? b0  : (z == 1) ? b1  : b2;
    float* dst        = (z == 0) ? g_i : (z == 1) ? g_f : g_cp;

    const int tid  = threadIdx.x;
    const int lane = tid & 31;
    const int wid  = tid >> 5;
    const int warp_m = wid & 1;    // 0..1 -> row offset *64
    const int warp_n = wid >> 1;   // 0..3 -> col offset *32
    const int grp = lane >> 2;     // 0..7
    const int qid = lane & 3;      // 0..3
    const int row0 = blockIdx.y * 128;
    const int n0   = blockIdx.x * 128;

    // staging mapping: thread covers rows r_s and r_s+64, 8 floats at kq8
    const int r_s = tid >> 2;          // 0..63
    const int kq8 = (tid & 3) * 8;     // 0,8,16,24

    const uint32_t smb = smem_u32(sm);
    const uint32_t sA0 = smb + ((uint32_t)r_s * LDS + kq8) * 4u;
    const uint32_t sB0 = smb + ((uint32_t)(128 + r_s) * LDS + kq8) * 4u;
    constexpr uint32_t ROW64 = 64u * LDS * 4u;
    constexpr uint32_t STG   = (uint32_t)STG_WORDS * 4u;

    float acc[4][4][4];
    #pragma unroll
    for (int i = 0; i < 4; i++)
        #pragma unroll
        for (int j = 0; j < 4; j++)
            #pragma unroll
            for (int v = 0; v < 4; v++) acc[i][j][v] = 0.0f;

    auto issue = [&](int cc, uint32_t buf) {
        const int kt = cc * 32;
        const float* seg = (kt < 1024) ? A0 : ((kt < 2048) ? A1 : A2);
        const int kin = (kt & 1023) + kq8;
        const uint32_t bo = buf * STG;
        const float* a0p = seg + (size_t)(row0 + r_s) * HD + kin;
        const float* a1p = seg + (size_t)(row0 + r_s + 64) * HD + kin;
        const float* b0p = Wt + (size_t)(n0 + r_s) * K + kt + kq8;
        const float* b1p = Wt + (size_t)(n0 + r_s + 64) * K + kt + kq8;
        cp16(sA0 + bo,              a0p);
        cp16(sA0 + bo + 16,         a0p + 4);
        cp16(sA0 + bo + ROW64,      a1p);
        cp16(sA0 + bo + ROW64 + 16, a1p + 4);
        cp16(sB0 + bo,              b0p);
        cp16(sB0 + bo + 16,         b0p + 4);
        cp16(sB0 + bo + ROW64,      b1p);
        cp16(sB0 + bo + ROW64 + 16, b1p + 4);
    };

    issue(0, 0);
    CP_COMMIT();

    for (int c = 0; c < NCH; c++) {
        const int p = c & 1;

        __syncthreads();   // all reads of buffer p (chunk c-2) are complete
        if (c + 1 < NCH) {
            issue(c + 1, p ^ 1);
            CP_COMMIT();
            asm volatile("cp.async.wait_group 1;" ::: "memory");  // chunk c landed
        } else {
            asm volatile("cp.async.wait_group 0;" ::: "memory");
        }
        __syncthreads();   // chunk c visible to all warps

        const float* Ab = sm + p * STG_WORDS;
        const float* Bb = Ab + 128 * LDS;

        #pragma unroll
        for (int kk = 0; kk < 32; kk += 8) {
            uint32_t af[4][4], bf[4][2];
            #pragma unroll
            for (int i = 0; i < 4; i++) {
                const int r = warp_m * 64 + i * 16 + grp;
                af[i][0] = __float_as_uint(Ab[(r)     * LDS + kk + qid]);
                af[i][1] = __float_as_uint(Ab[(r + 8) * LDS + kk + qid]);
                af[i][2] = __float_as_uint(Ab[(r)     * LDS + kk + qid + 4]);
                af[i][3] = __float_as_uint(Ab[(r + 8) * LDS + kk + qid + 4]);
            }
            #pragma unroll
            for (int j = 0; j < 4; j++) {
                const int n = warp_n * 32 + j * 8 + grp;
                bf[j][0] = __float_as_uint(Bb[n * LDS + kk + qid]);
                bf[j][1] = __float_as_uint(Bb[n * LDS + kk + qid + 4]);
            }
            #pragma unroll
            for (int i = 0; i < 4; i++)
                #pragma unroll
                for (int j = 0; j < 4; j++)
                    mma8(acc[i][j][0], acc[i][j][1], acc[i][j][2], acc[i][j][3],
                         af[i][0], af[i][1], af[i][2], af[i][3],
                         bf[j][0], bf[j][1]);
        }
    }

    // epilogue
    const bool is_sig = (z < 2);
    #pragma unroll
    for (int i = 0; i < 4; i++) {
        const size_t r = (size_t)(row0 + warp_m * 64 + i * 16 + grp);
        #pragma unroll
        for (int j = 0; j < 4; j++) {
            const int n = n0 + warp_n * 32 + j * 8 + qid * 2;
            #pragma unroll
            for (int v = 0; v < 4; v++) {
                const size_t rr = r + (v >= 2 ? 8 : 0);
                const int nn = n + (v & 1);
                float val = acc[i][j][v] + __ldg(bias + nn);
                dst[rr * HD + nn] = is_sig ? sigm(val) : tanhf(val);
            }
        }
    }
}

// ---------------------------------------------------------------------------
// c_new = f*c + i*cp  -> g_cnew (exact), g_cnr (tf32). dout written by gemm_o.
// ---------------------------------------------------------------------------
__global__ __launch_bounds__(256) void cnew_kernel(const float* __restrict__ c)
{
    const size_t i = ((size_t)blockIdx.x * 256 + threadIdx.x) * 4;
    float4 f4 = *reinterpret_cast<const float4*>(g_f + i);
    float4 i4 = *reinterpret_cast<const float4*>(g_i + i);
    float4 p4 = *reinterpret_cast<const float4*>(g_cp + i);
    float4 c4 = *reinterpret_cast<const float4*>(c + i);
    float4 cn;
    cn.x = fmaf(f4.x, c4.x, i4.x * p4.x);
    cn.y = fmaf(f4.y, c4.y, i4.y * p4.y);
    cn.z = fmaf(f4.z, c4.z, i4.z * p4.z);
    cn.w = fmaf(f4.w, c4.w, i4.w * p4.w);
    *reinterpret_cast<float4*>(g_cnew + i) = cn;
    *reinterpret_cast<float4*>(g_cnr + i) = tf32_round4(cn);
}

// ---------------------------------------------------------------------------
// o-gate GEMM: [x,h,cnew_r]@Wo -> h_new = sig(o)*tanh(cnew).
// Writes h_new AND c_new into dout (epilogue already loads g_cnew). K=3072.
// Same BK=32 double-buffer pattern as gemm_gates.
// ---------------------------------------------------------------------------
__global__ __launch_bounds__(256, 2) void gemm_o(
    const float* __restrict__ A0, const float* __restrict__ A1,
    const float* __restrict__ A2, const float* __restrict__ Wt,
    const float* __restrict__ bias, float* __restrict__ dout)
{
    constexpr int K   = 3072;
    constexpr int NCH = K / 32;
    constexpr int LDS = 36;
    constexpr int STG_WORDS = 256 * LDS;

    extern __shared__ __align__(16) float sm[];

    const int tid  = threadIdx.x;
    const int lane = tid & 31;
    const int wid  = tid >> 5;
    const int warp_m = wid & 1;
    const int warp_n = wid >> 1;
    const int grp = lane >> 2;
    const int qid = lane & 3;
    const int row0 = blockIdx.y * 128;
    const int n0   = blockIdx.x * 128;

    const int r_s = tid >> 2;
    const int kq8 = (tid & 3) * 8;

    const uint32_t smb = smem_u32(sm);
    const uint32_t sA0 = smb + ((uint32_t)r_s * LDS + kq8) * 4u;
    const uint32_t sB0 = smb + ((uint32_t)(128 + r_s) * LDS + kq8) * 4u;
    constexpr uint32_t ROW64 = 64u * LDS * 4u;
    constexpr uint32_t STG   = (uint32_t)STG_WORDS * 4u;

    float acc[4][4][4];
    #pragma unroll
    for (int i = 0; i < 4; i++)
        #pragma unroll
        for (int j = 0; j < 4; j++)
            #pragma unroll
            for (int v = 0; v < 4; v++) acc[i][j][v] = 0.0f;

    auto issue = [&](int cc, uint32_t buf) {
        const int kt = cc * 32;
        const float* seg = (kt < 1024) ? A0 : ((kt < 2048) ? A1 : A2);
        const int kin = (kt & 1023) + kq8;
        const uint32_t bo = buf * STG;
        const float* a0p = seg + (size_t)(row0 + r_s) * HD + kin;
        const float* a1p = seg + (size_t)(row0 + r_s + 64) * HD + kin;
        const float* b0p = Wt + (size_t)(n0 + r_s) * K + kt + kq8;
        const float* b1p = Wt + (size_t)(n0 + r_s + 64) * K + kt + kq8;
        cp16(sA0 + bo,              a0p);
        cp16(sA0 + bo + 16,         a0p + 4);
        cp16(sA0 + bo + ROW64,      a1p);
        cp16(sA0 + bo + ROW64 + 16, a1p + 4);
        cp16(sB0 + bo,              b0p);
        cp16(sB0 + bo + 16,         b0p + 4);
        cp16(sB0 + bo + ROW64,      b1p);
        cp16(sB0 + bo + ROW64 + 16, b1p + 4);
    };

    issue(0, 0);
    CP_COMMIT();

    for (int c = 0; c < NCH; c++) {
        const int p = c & 1;

        __syncthreads();
        if (c + 1 < NCH) {
            issue(c + 1, p ^ 1);
            CP_COMMIT();
            asm volatile("cp.async.wait_group 1;" ::: "memory");
        } else {
            asm volatile("cp.async.wait_group 0;" ::: "memory");
        }
        __syncthreads();

        const float* Ab = sm + p * STG_WORDS;
        const float* Bb = Ab + 128 * LDS;

        #pragma unroll
        for (int kk = 0; kk < 32; kk += 8) {
            uint32_t af[4][4], bf[4][2];
            #pragma unroll
            for (int i = 0; i < 4; i++) {
                const int r = warp_m * 64 + i * 16 + grp;
                af[i][0] = __float_as_uint(Ab[(r)     * LDS + kk + qid]);
                af[i][1] = __float_as_uint(Ab[(r + 8) * LDS + kk + qid]);
                af[i][2] = __float_as_uint(Ab[(r)     * LDS + kk + qid + 4]);
                af[i][3] = __float_as_uint(Ab[(r + 8) * LDS + kk + qid + 4]);
            }
            #pragma unroll
            for (int j = 0; j < 4; j++) {
                const int n = warp_n * 32 + j * 8 + grp;
                bf[j][0] = __float_as_uint(Bb[n * LDS + kk + qid]);
                bf[j][1] = __float_as_uint(Bb[n * LDS + kk + qid + 4]);
            }
            #pragma unroll
            for (int i = 0; i < 4; i++)
                #pragma unroll
                for (int j = 0; j < 4; j++)
                    mma8(acc[i][j][0], acc[i][j][1], acc[i][j][2], acc[i][j][3],
                         af[i][0], af[i][1], af[i][2], af[i][3],
                         bf[j][0], bf[j][1]);
        }
    }

    #pragma unroll
    for (int i = 0; i < 4; i++) {
        const size_t r = (size_t)(row0 + warp_m * 64 + i * 16 + grp);
        #pragma unroll
        for (int j = 0; j < 4; j++) {
            const int n = n0 + warp_n * 32 + j * 8 + qid * 2;
            #pragma unroll
            for (int v = 0; v < 4; v++) {
                const size_t rr = r + (v >= 2 ? 8 : 0);
                const int nn = n + (v & 1);
                float val = acc[i][j][v] + __ldg(bias + nn);
                float cn = g_cnew[rr * HD + nn];
                float hn = sigm(val) * tanhf(cn);
                g_hnew[rr * HD + nn] = hn;
                dout[rr * OUTW + nn] = hn;
                dout[rr * OUTW + HD + nn] = cn;
            }
        }
    }
}

// ---------------------------------------------------------------------------
// micro = h_new @ W_m + b_m : [8192,1024] @ [1024,64]  (FFMA, small)
// ---------------------------------------------------------------------------
__global__ __launch_bounds__(256) void micro_gemm(const float* __restrict__ Wm,
                                                  const float* __restrict__ bm)
{
    __shared__ __align__(16) float As2[16][68];
    __shared__ __align__(16) float Bs2[16][64];

    const int tid  = threadIdx.x;
    const int row0 = blockIdx.x * 64;
    const int arow = tid >> 2;
    const int acol = (tid & 3) * 4;
    const int brow = tid >> 4;
    const int bcol = (tid & 15) * 4;
    const int ty   = tid >> 4;
    const int tx   = tid & 15;

    float acc[4][4];
    #pragma unroll
    for (int i = 0; i < 4; i++)
        #pragma unroll
        for (int j = 0; j < 4; j++) acc[i][j] = 0.0f;

    for (int kt = 0; kt < 1024; kt += 16) {
        float4 av = *reinterpret_cast<const float4*>(
            g_hnew + (size_t)(row0 + arow) * HD + kt + acol);
        As2[acol + 0][arow] = av.x;
        As2[acol + 1][arow] = av.y;
        As2[acol + 2][arow] = av.z;
        As2[acol + 3][arow] = av.w;
        *reinterpret_cast<float4*>(&Bs2[brow][bcol]) =
            *reinterpret_cast<const float4*>(Wm + (size_t)(kt + brow) * 64 + bcol);
        __syncthreads();

        #pragma unroll
        for (int k = 0; k < 16; k++) {
            float4 a = *reinterpret_cast<const float4*>(&As2[k][ty * 4]);
            float4 b = *reinterpret_cast<const float4*>(&Bs2[k][tx * 4]);
            float ar[4] = {a.x, a.y, a.z, a.w};
            float br[4] = {b.x, b.y, b.z, b.w};
            #pragma unroll
            for (int i = 0; i < 4; i++)
                #pragma unroll
                for (int j = 0; j < 4; j++)
                    acc[i][j] = fmaf(ar[i], br[j], acc[i][j]);
        }
        __syncthreads();
    }

    #pragma unroll
    for (int i = 0; i < 4; i++) {
        const int r = row0 + ty * 4 + i;
        #pragma unroll
        for (int j = 0; j < 4; j++) {
            const int n = tx * 4 + j;
            g_micro[(size_t)r * 64 + n] = acc[i][j] + bm[n];
        }
    }
}

// ---------------------------------------------------------------------------
// Tail: gumbel-softmax attention + alpha/beta (one block per batch row)
// ---------------------------------------------------------------------------
__global__ __launch_bounds__(128) void tail_kernel(
    const float* __restrict__ x, const float* __restrict__ memory,
    const float* __restrict__ u_gs, const float* __restrict__ u_a,
    const float* __restrict__ u_b,
    const float* __restrict__ w_a_h, const float* __restrict__ w_a_x,
    const float* __restrict__ w_a_r,
    const float* __restrict__ w_b_h, const float* __restrict__ w_b_x,
    const float* __restrict__ w_b_r,
    float* __restrict__ dout)
{
    const int b = blockIdx.x;
    const int t = threadIdx.x;

    __shared__ float smicro[64];
    __shared__ float slog[16];
    __shared__ float sattn[16];
    __shared__ float ssamp[64];
    __shared__ float red[6 * 128];

    const float* mem = memory + (size_t)b * 16 * 64;

    if (t < 64) smicro[t] = g_micro[(size_t)b * 64 + t];
    __syncthreads();

    if (t < 16) {
        float a = 0.0f;
        #pragma unroll 8
        for (int k = 0; k < 64; k++) a = fmaf(mem[t * 64 + k], smicro[k], a);
        float u = u_gs[b * 16 + t];
        slog[t] = a + (-logf(-logf(u)));
    }
    __syncthreads();

    if (t == 0) {
        float mx = -1e30f;
        for (int m = 0; m < 16; m++) mx = fmaxf(mx, slog[m]);
        float e[16], s = 0.0f;
        for (int m = 0; m < 16; m++) { e[m] = expf(slog[m] - mx); s += e[m]; }
        float inv = 1.0f / s;
        for (int m = 0; m < 16; m++) sattn[m] = e[m] * inv;
    }
    __syncthreads();

    if (t < 64) {
        float s = 0.0f;
        #pragma unroll
        for (int m = 0; m < 16; m++) s = fmaf(mem[m * 64 + t], sattn[m], s);
        ssamp[t] = s + 1.0f;
    }
    __syncthreads();

    const float* hrow = g_hnew + (size_t)b * HD;
    const float* xrow = x + (size_t)b * HD;
    float pah = 0.f, pax = 0.f, pbh = 0.f, pbx = 0.f, par = 0.f, pbr = 0.f;
    for (int k = t; k < HD; k += 128) {
        float hv = hrow[k], xv = xrow[k];
        pah = fmaf(hv, w_a_h[k], pah);
        pbh = fmaf(hv, w_b_h[k], pbh);
        pax = fmaf(xv, w_a_x[k], pax);
        pbx = fmaf(xv, w_b_x[k], pbx);
    }
    if (t < 64) {
        float sv = ssamp[t];
        par = sv * w_a_r[t];
        pbr = sv * w_b_r[t];
    }
    red[0 * 128 + t] = pah;
    red[1 * 128 + t] = pax;
    red[2 * 128 + t] = par;
    red[3 * 128 + t] = pbh;
    red[4 * 128 + t] = pbx;
    red[5 * 128 + t] = pbr;
    __syncthreads();

    for (int s = 64; s > 0; s >>= 1) {
        if (t < s) {
            #pragma unroll
            for (int v = 0; v < 6; v++) red[v * 128 + t] += red[v * 128 + t + s];
        }
        __syncthreads();
    }

    if (t == 0) {
        float ua = u_a[b], ub = u_b[b];
        float la = logf(ua) - log1pf(-ua);
        float lb = logf(ub) - log1pf(-ub);
        float alpha = sigm(red[0] + red[128] + red[256] + la);
        float beta  = sigm(red[384] + red[512] + red[640] + lb);
        dout[(size_t)b * OUTW + 2048] = alpha;
        dout[(size_t)b * OUTW + 2049] = beta;
    }
}

// ---------------------------------------------------------------------------
extern "C" void kernel_launch(void* const* d_in, const int* in_sizes, int n_in,
                              void* d_out, int out_size)
{
    const float* x      = (const float*)d_in[0];
    const float* h      = (const float*)d_in[1];
    const float* c      = (const float*)d_in[2];
    const float* memory = (const float*)d_in[3];
    const float* u_gs   = (const float*)d_in[4];
    const float* u_a    = (const float*)d_in[5];
    const float* u_b    = (const float*)d_in[6];
    const float* W_i    = (const float*)d_in[7];
    const float* b_i    = (const float*)d_in[8];
    const float* W_f    = (const float*)d_in[9];
    const float* b_f    = (const float*)d_in[10];
    const float* W_o    = (const float*)d_in[11];
    const float* b_o    = (const float*)d_in[12];
    const float* W_cand = (const float*)d_in[13];
    const float* b_cand = (const float*)d_in[14];
    const float* W_m    = (const float*)d_in[15];
    const float* b_m    = (const float*)d_in[16];
    const float* w_a_h  = (const float*)d_in[17];
    const float* w_a_x  = (const float*)d_in[18];
    const float* w_a_r  = (const float*)d_in[19];
    const float* w_b_h  = (const float*)d_in[20];
    const float* w_b_x  = (const float*)d_in[21];
    const float* w_b_r  = (const float*)d_in[22];
    float* out = (float*)d_out;

    float* wt_i; cudaGetSymbolAddress((void**)&wt_i, g_Wt_i);
    float* wt_f; cudaGetSymbolAddress((void**)&wt_f, g_Wt_f);
    float* wt_o; cudaGetSymbolAddress((void**)&wt_o, g_Wt_o);
    float* wt_c; cudaGetSymbolAddress((void**)&wt_c, g_Wt_c);
    float* xr;   cudaGetSymbolAddress((void**)&xr,   g_xr);
    float* hr;   cudaGetSymbolAddress((void**)&hr,   g_hr);
    float* cr;   cudaGetSymbolAddress((void**)&cr,   g_cr);
    float* cnr;  cudaGetSymbolAddress((void**)&cnr,  g_cnr);

    const int SMEM_DYN = 2 * 256 * 36 * 4;  // 73728 bytes (2-stage, BK=32)
    static bool attr_set = false;
    if (!attr_set) {
        cudaFuncSetAttribute(gemm_gates, cudaFuncAttributeMaxDynamicSharedMemorySize, SMEM_DYN);
        cudaFuncSetAttribute(gemm_o,     cudaFuncAttributeMaxDynamicSharedMemorySize, SMEM_DYN);
        attr_set = true;
    }

    round_xhc<<<(NB * HD) / (256 * 4), 256>>>(x, h, c);
    transW_all<<<dim3(32, 96, 4), dim3(32, 8)>>>(W_i, W_f, W_o, W_cand,
                                                 wt_i, wt_f, wt_o, wt_c);

    // merged i/f/cand gates (cand last in dispatch order)
    gemm_gates<<<dim3(8, 64, 3), 256, SMEM_DYN>>>(xr, hr, cr, wt_i, wt_f, wt_c,
                                                  b_i, b_f, b_cand);
    cnew_kernel<<<(NB * HD) / (256 * 4), 256>>>(c);
    gemm_o<<<dim3(8, 64), 256, SMEM_DYN>>>(xr, hr, cnr, wt_o, b_o, out);
    micro_gemm<<<NB / 64, 256>>>(W_m, b_m);
    tail_kernel<<<NB, 128>>>(x, memory, u_gs, u_a, u_b,
                             w_a_h, w_a_x, w_a_r, w_b_h, w_b_x, w_b_r, out);
}